// round 10
// baseline (speedup 1.0000x reference)
#include <cuda_runtime.h>

#define PD     512        // protein_dim == drug_dim
#define NSEG   2000       // neighbors per layer
#define EDG    300000     // edges per layer
#define NSEG2  (2*NSEG)   // 4000 total segments
#define CAP    1024       // per-segment bucket capacity (avg fill ~150)
#define ACCB   (NSEG2/2)  // accum blocks in mega kernel (2 segments each)
#define ATTB   (NSEG2/4)  // attention blocks in mega kernel (4 rows each)
#define NPART  200        // vprior partial blocks
#define RPB    (NSEG2/NPART)  // 20 rows per vprior block
#define BASELINE 6.0f
#define LN_EPS 1e-5f

// ---------------- device scratch (no allocations allowed) ----------------
__device__ int   g_counts[NSEG2];
__device__ int2  g_ew[NSEG2 * CAP];   // {drug index, weight bits}, fixed-cap buckets
__device__ float g_logits[NSEG2];     // logits, overwritten in-place with softmax weights
__device__ float g_tpart[128];        // fixed part of attention hidden (target + layer_emb)
__device__ float g_vpart[NPART][PD];  // atomic-free vprior partials
__device__ int   g_aticket = 0;       // attention-block completion ticket (self-resetting)

// ---------------- K0: zero counts (block 0) + attention fixed part (block 1) --------
__global__ void k_init_tpart(const float* __restrict__ target, const float* __restrict__ lemb,
                             const float* __restrict__ W1, const float* __restrict__ b1) {
    int t = threadIdx.x;
    if (blockIdx.x == 0) {
        for (int i = t; i < NSEG2; i += 512) g_counts[i] = 0;
    } else {
        if (t < 128) {
            int l = t >> 6, j = t & 63;
            float acc = b1[j];
            for (int k = 0; k < PD; k++) acc += target[k] * W1[k * 64 + j];
            for (int k = 0; k < 16; k++) acc += lemb[l * 16 + k] * W1[(2 * PD + k) * 64 + j];
            g_tpart[t] = acc;
        }
    }
}

// ---------------- K1: fused hist + direct scatter, 16 edges per thread -------------
__global__ void __launch_bounds__(256) k_histscatter(const int* __restrict__ nb_form,
                                                     const int* __restrict__ nb_role,
                                                     const int* __restrict__ ei_form,
                                                     const float* __restrict__ y_form,
                                                     const int* __restrict__ ei_role,
                                                     const float* __restrict__ y_role) {
    __shared__ int s_nb[NSEG];
    const int layer = blockIdx.y;
    const int*   nb = layer ? nb_role : nb_form;
    const int*   ei = layer ? ei_role : ei_form;
    const float* yv = layer ? y_role  : y_form;
    for (int i = threadIdx.x; i < NSEG; i += 256) s_nb[i] = nb[i];
    __syncthreads();

    int e0 = (blockIdx.x * 256 + threadIdx.x) * 16;
    if (e0 >= EDG) return;                         // EDG % 16 == 0 (300000? no!) guard below
    int s[16], ds[16];
    float ys[16];
    #pragma unroll
    for (int q = 0; q < 4; q++) {                  // 4x int4 per stream, bounds-safe
        int base = e0 + q * 4;
        if (base + 3 < EDG) {
            int4 sv = *(const int4*)(ei + base);
            int4 dv = *(const int4*)(ei + EDG + base);
            float4 yy = *(const float4*)(yv + base);
            s[q*4+0]=sv.x; s[q*4+1]=sv.y; s[q*4+2]=sv.z; s[q*4+3]=sv.w;
            ds[q*4+0]=dv.x; ds[q*4+1]=dv.y; ds[q*4+2]=dv.z; ds[q*4+3]=dv.w;
            ys[q*4+0]=yy.x; ys[q*4+1]=yy.y; ys[q*4+2]=yy.z; ys[q*4+3]=yy.w;
        } else {
            #pragma unroll
            for (int j = 0; j < 4; j++) {
                int e = base + j;
                s[q*4+j]  = (e < EDG) ? ei[e] : -1;          // -1 never matches nb (>=0 ids)
                ds[q*4+j] = (e < EDG) ? ei[EDG + e] : 0;
                ys[q*4+j] = (e < EDG) ? yv[e] : 0.f;
            }
        }
    }
    int lo[16];
    #pragma unroll
    for (int j = 0; j < 16; j++) lo[j] = 0;
    // branch-free lower_bound, 16 searches interleaved for latency overlap
    #pragma unroll
    for (int step = 1024; step > 0; step >>= 1) {
        #pragma unroll
        for (int j = 0; j < 16; j++) {
            int c = lo[j] + step;
            if (c <= NSEG && s_nb[c - 1] < s[j]) lo[j] = c;
        }
    }
    #pragma unroll
    for (int j = 0; j < 16; j++) {
        int pos = lo[j] < NSEG ? lo[j] : NSEG - 1;   // clip (searchsorted semantics)
        if (s_nb[pos] == s[j]) {
            int seg  = layer * NSEG + pos;
            int rank = atomicAdd(&g_counts[seg], 1);
            if (rank < CAP)
                g_ew[(seg << 10) + rank] = make_int2(ds[j], __float_as_int(ys[j] - BASELINE));
        }
    }
}

// ---------------- K2: mega kernel — accum + attention (+softmax on last attn block) -
__global__ void __launch_bounds__(256) k_mega(const float4* __restrict__ drugs,
                                              float4* __restrict__ msgs,
                                              const float* __restrict__ form_f,
                                              const float* __restrict__ role_f,
                                              const float* __restrict__ W1,
                                              const float* __restrict__ W2,
                                              const float* __restrict__ b2) {
    __shared__ float sf[4][PD];
    __shared__ float sred[4][2];
    if (blockIdx.x < ACCB) {
        // ---- gather + accumulate: 2 segments per block, 128 threads each ----
        int t = threadIdx.x & 127;
        int seg = blockIdx.x * 2 + (threadIdx.x >> 7);
        int cnt = min(g_counts[seg], CAP);
        const int2* ew = g_ew + (seg << 10);       // 16B-aligned base
        float4 a0 = {0.f,0.f,0.f,0.f}, a1 = a0, a2 = a0, a3 = a0;
        int e = 0;
        for (; e + 7 < cnt; e += 8) {
            int4 p0 = *(const int4*)(ew + e);
            int4 p1 = *(const int4*)(ew + e + 2);
            int4 p2 = *(const int4*)(ew + e + 4);
            int4 p3 = *(const int4*)(ew + e + 6);
            float4 r0 = drugs[(size_t)p0.x * 128 + t];
            float4 r1 = drugs[(size_t)p0.z * 128 + t];
            float4 r2 = drugs[(size_t)p1.x * 128 + t];
            float4 r3 = drugs[(size_t)p1.z * 128 + t];
            float4 r4 = drugs[(size_t)p2.x * 128 + t];
            float4 r5 = drugs[(size_t)p2.z * 128 + t];
            float4 r6 = drugs[(size_t)p3.x * 128 + t];
            float4 r7 = drugs[(size_t)p3.z * 128 + t];
            float w0 = __int_as_float(p0.y), w1 = __int_as_float(p0.w);
            float w2 = __int_as_float(p1.y), w3 = __int_as_float(p1.w);
            float w4 = __int_as_float(p2.y), w5 = __int_as_float(p2.w);
            float w6 = __int_as_float(p3.y), w7 = __int_as_float(p3.w);
            a0.x += w0*r0.x; a0.y += w0*r0.y; a0.z += w0*r0.z; a0.w += w0*r0.w;
            a1.x += w1*r1.x; a1.y += w1*r1.y; a1.z += w1*r1.z; a1.w += w1*r1.w;
            a2.x += w2*r2.x; a2.y += w2*r2.y; a2.z += w2*r2.z; a2.w += w2*r2.w;
            a3.x += w3*r3.x; a3.y += w3*r3.y; a3.z += w3*r3.z; a3.w += w3*r3.w;
            a0.x += w4*r4.x; a0.y += w4*r4.y; a0.z += w4*r4.z; a0.w += w4*r4.w;
            a1.x += w5*r5.x; a1.y += w5*r5.y; a1.z += w5*r5.z; a1.w += w5*r5.w;
            a2.x += w6*r6.x; a2.y += w6*r6.y; a2.z += w6*r6.z; a2.w += w6*r6.w;
            a3.x += w7*r7.x; a3.y += w7*r7.y; a3.z += w7*r7.z; a3.w += w7*r7.w;
        }
        for (; e < cnt; e++) {
            int2 p = ew[e];
            float w = __int_as_float(p.y);
            float4 r = drugs[(size_t)p.x * 128 + t];
            a0.x += w*r.x; a0.y += w*r.y; a0.z += w*r.z; a0.w += w*r.w;
        }
        a0.x += a1.x + a2.x + a3.x;
        a0.y += a1.y + a2.y + a3.y;
        a0.z += a1.z + a2.z + a3.z;
        a0.w += a1.w + a2.w + a3.w;
        msgs[(size_t)seg * 128 + t] = a0;
    } else {
        // ---- attention logits: 4 rows per block, 64 threads per row ----
        int g = threadIdx.x >> 6;
        int t = threadIdx.x & 63;
        int row = (blockIdx.x - ACCB) * 4 + g;
        int l = (row >= NSEG) ? 1 : 0;
        const float* feat = l ? role_f + (size_t)(row - NSEG) * PD
                              : form_f + (size_t)row * PD;
        float4* s4 = (float4*)sf[g];
        const float4* f4 = (const float4*)feat;
        s4[t]      = f4[t];
        s4[t + 64] = f4[t + 64];
        __syncthreads();
        float acc = g_tpart[l * 64 + t];
        const float* Wp = W1 + PD * 64 + t;        // rows 512..1023 of W1, column t
        const float4* sfv = (const float4*)sf[g];
        #pragma unroll 4
        for (int k4 = 0; k4 < PD / 4; k4++) {
            float4 s = sfv[k4];
            int k = k4 * 4;
            acc += s.x * Wp[k * 64] + s.y * Wp[(k + 1) * 64]
                 + s.z * Wp[(k + 2) * 64] + s.w * Wp[(k + 3) * 64];
        }
        acc = acc > 0.f ? acc : 0.2f * acc;        // LeakyReLU(0.2)
        float p = acc * W2[t];
        #pragma unroll
        for (int o = 16; o > 0; o >>= 1) p += __shfl_down_sync(0xffffffffu, p, o);
        if ((t & 31) == 0) sred[g][t >> 5] = p;
        __syncthreads();
        if (t == 0) g_logits[row] = sred[g][0] + sred[g][1] + b2[0];

        // ---- last attention block converts logits -> softmax weights in-place.
        //      Runs inside the shadow of the long accum blocks: effectively free.
        __shared__ unsigned s_last;
        __shared__ float s_r[8];
        __syncthreads();
        __threadfence();
        if (threadIdx.x == 0)
            s_last = (atomicAdd(&g_aticket, 1) == (ATTB - 1)) ? 1u : 0u;
        __syncthreads();
        if (!s_last) return;
        __threadfence();                       // order our logit reads after others' writes
        int tt = threadIdx.x;                  // 256 threads
        int lane = tt & 31, warp = tt >> 5;
        if (tt == 0) g_aticket = 0;            // reset for next graph replay
        float m = -1e30f;
        for (int i = tt; i < NSEG2; i += 256) m = fmaxf(m, g_logits[i]);
        #pragma unroll
        for (int o = 16; o > 0; o >>= 1) m = fmaxf(m, __shfl_xor_sync(0xffffffffu, m, o));
        if (lane == 0) s_r[warp] = m;
        __syncthreads();
        float mx = s_r[0];
        #pragma unroll
        for (int w = 1; w < 8; w++) mx = fmaxf(mx, s_r[w]);
        float ssum = 0.f;
        for (int i = tt; i < NSEG2; i += 256) ssum += expf(g_logits[i] - mx);
        #pragma unroll
        for (int o = 16; o > 0; o >>= 1) ssum += __shfl_xor_sync(0xffffffffu, ssum, o);
        __syncthreads();
        if (lane == 0) s_r[warp] = ssum;
        __syncthreads();
        float tot = 0.f;
        #pragma unroll
        for (int w = 0; w < 8; w++) tot += s_r[w];
        float inv = 1.f / tot;
        for (int i = tt; i < NSEG2; i += 256) g_logits[i] = expf(g_logits[i] - mx) * inv;
    }
}

// ---------------- K3: vprior partials — pure streaming, atomic-free ----------------
__global__ void __launch_bounds__(128) k_vprior(const float4* __restrict__ msgs) {
    int t = threadIdx.x;
    int r0 = blockIdx.x * RPB;
    float4 a = {0.f, 0.f, 0.f, 0.f};
    #pragma unroll
    for (int j = 0; j < RPB; j++) {       // fully unrolled: all 40 loads in flight
        float w = g_logits[r0 + j];       // already softmax-normalized
        float4 v = __ldcs(&msgs[(size_t)(r0 + j) * 128 + t]);
        a.x += w * v.x; a.y += w * v.y; a.z += w * v.z; a.w += w * v.w;
    }
    *(float4*)&g_vpart[blockIdx.x][t * 4] = a;
}

// ---------------- K4: reduce partials + MLP + residual + LayerNorm -----------------
__global__ void __launch_bounds__(512) k_final(const float* __restrict__ target,
                                               const float* __restrict__ Wi1,
                                               const float* __restrict__ bi1,
                                               const float* __restrict__ alpha_p,
                                               const float* __restrict__ Wi2,
                                               const float* __restrict__ bi2,
                                               const float* __restrict__ gamma,
                                               const float* __restrict__ beta,
                                               float* __restrict__ out) {
    __shared__ float sv[PD];
    __shared__ float sh[PD];
    __shared__ float sred[512];
    int t = threadIdx.x;
    float s = 0.f;
    #pragma unroll 8
    for (int p = 0; p < NPART; p++) s += g_vpart[p][t];   // coalesced across threads
    sv[t] = s;
    __syncthreads();
    float h = bi1[t];
    #pragma unroll 8
    for (int k = 0; k < PD; k++) h += sv[k] * Wi1[k * PD + t];
    float alpha = alpha_p[0];
    h = h > 0.f ? h : alpha * h;          // PReLU
    sh[t] = h;
    __syncthreads();
    float v = bi2[t];
    #pragma unroll 8
    for (int k = 0; k < PD; k++) v += sh[k] * Wi2[k * PD + t];
    float x = target[t] + v;
    sred[t] = x; __syncthreads();
    for (int o = 256; o > 0; o >>= 1) { if (t < o) sred[t] += sred[t + o]; __syncthreads(); }
    float mu = sred[0] * (1.f / PD);
    __syncthreads();
    float d = x - mu;
    sred[t] = d * d; __syncthreads();
    for (int o = 256; o > 0; o >>= 1) { if (t < o) sred[t] += sred[t + o]; __syncthreads(); }
    float var = sred[0] * (1.f / PD);
    out[t] = (x - mu) * rsqrtf(var + LN_EPS) * gamma[t] + beta[t];
}

// ---------------- launch ----------------
extern "C" void kernel_launch(void* const* d_in, const int* in_sizes, int n_in,
                              void* d_out, int out_size) {
    const float* target = (const float*)d_in[0];
    const float* form_f = (const float*)d_in[1];
    const float* role_f = (const float*)d_in[2];
    const int*   nb_form = (const int*)d_in[3];
    const int*   nb_role = (const int*)d_in[4];
    const int*   ei_form = (const int*)d_in[5];
    const float* y_form  = (const float*)d_in[6];
    const int*   ei_role = (const int*)d_in[7];
    const float* y_role  = (const float*)d_in[8];
    const float* drugs   = (const float*)d_in[9];
    const float* lemb    = (const float*)d_in[10];
    const float* W1      = (const float*)d_in[11];
    const float* b1      = (const float*)d_in[12];
    const float* W2      = (const float*)d_in[13];
    const float* b2      = (const float*)d_in[14];
    const float* Wi1     = (const float*)d_in[15];
    const float* bi1     = (const float*)d_in[16];
    const float* alpha   = (const float*)d_in[17];
    const float* Wi2     = (const float*)d_in[18];
    const float* bi2     = (const float*)d_in[19];
    const float* gamma   = (const float*)d_in[20];
    const float* beta    = (const float*)d_in[21];

    float* out  = (float*)d_out;
    float* msgs = out + PD;   // [4000, 512]: form rows 0..1999, role rows 2000..3999

    k_init_tpart<<<2, 512>>>(target, lemb, W1, b1);

    dim3 gE16((EDG / 16 + 255) / 256, 2);   // 16 edges per thread
    k_histscatter<<<gE16, 256>>>(nb_form, nb_role, ei_form, y_form, ei_role, y_role);
    k_mega<<<ACCB + ATTB, 256>>>((const float4*)drugs, (float4*)msgs,
                                 form_f, role_f, W1, W2, b2);
    k_vprior<<<NPART, 128>>>((const float4*)msgs);
    k_final<<<1, 512>>>(target, Wi1, bi1, alpha, Wi2, bi2, gamma, beta, out);
}

// round 11
// speedup vs baseline: 1.1309x; 1.1309x over previous
#include <cuda_runtime.h>

#define PD     512        // protein_dim == drug_dim
#define NSEG   2000       // neighbors per layer
#define EDG    300000     // edges per layer
#define NSEG2  (2*NSEG)   // 4000 total segments
#define CAP    1024       // per-segment bucket capacity (avg fill ~150)
#define ACCB   (NSEG2/2)  // accum blocks in mega kernel (2 segments each)
#define ATTB   (NSEG2/4)  // attention blocks in mega kernel (4 rows each)
#define NPART  200        // vprior partial blocks
#define RPB    (NSEG2/NPART)  // 20 rows per vprior block
#define BASELINE 6.0f
#define LN_EPS 1e-5f

// ---------------- device scratch (no allocations allowed) ----------------
__device__ int   g_counts[NSEG2];     // statically zero; re-zeroed by k_vprior each call
__device__ int2  g_ew[NSEG2 * CAP];   // {drug index, weight bits}, fixed-cap buckets
__device__ float g_logits[NSEG2];     // logits, overwritten in-place with softmax weights
__device__ float g_tpart[128];        // fixed part of attention hidden (target + layer_emb)
__device__ float g_vpart[NPART][PD];  // atomic-free vprior partials
__device__ int   g_aticket = 0;       // attention-block completion ticket (self-resetting)

// ---------------- K1: fused hist+scatter (y=0,1) and tpart (y=2) -------------------
__global__ void __launch_bounds__(256) k_histscatter(const int* __restrict__ nb_form,
                                                     const int* __restrict__ nb_role,
                                                     const int* __restrict__ ei_form,
                                                     const float* __restrict__ y_form,
                                                     const int* __restrict__ ei_role,
                                                     const float* __restrict__ y_role,
                                                     const float* __restrict__ target,
                                                     const float* __restrict__ lemb,
                                                     const float* __restrict__ W1,
                                                     const float* __restrict__ b1) {
    const int layer = blockIdx.y;
    if (layer == 2) {
        // ---- attention fixed part: 1 block, 128 active threads ----
        if (blockIdx.x != 0) return;
        int t = threadIdx.x;
        if (t >= 128) return;
        int l = t >> 6, j = t & 63;
        float acc = b1[j];
        for (int k = 0; k < PD; k++) acc += target[k] * W1[k * 64 + j];
        for (int k = 0; k < 16; k++)  acc += lemb[l * 16 + k] * W1[(2 * PD + k) * 64 + j];
        g_tpart[t] = acc;
        return;
    }
    __shared__ int s_nb[NSEG];
    const int*   nb = layer ? nb_role : nb_form;
    const int*   ei = layer ? ei_role : ei_form;
    const float* yv = layer ? y_role  : y_form;
    for (int i = threadIdx.x; i < NSEG; i += 256) s_nb[i] = nb[i];
    __syncthreads();

    int e0 = (blockIdx.x * 256 + threadIdx.x) * 8;
    if (e0 >= EDG) return;                         // EDG % 8 == 0, full int4 pairs safe
    int4 va = *(const int4*)(ei + e0);             // ei[0][e0..]
    int4 vb = *(const int4*)(ei + e0 + 4);
    int4 da = *(const int4*)(ei + EDG + e0);       // ei[1][e0..]
    int4 db = *(const int4*)(ei + EDG + e0 + 4);
    float4 ya = *(const float4*)(yv + e0);
    float4 yb = *(const float4*)(yv + e0 + 4);
    int s[8]  = {va.x, va.y, va.z, va.w, vb.x, vb.y, vb.z, vb.w};
    int ds[8] = {da.x, da.y, da.z, da.w, db.x, db.y, db.z, db.w};
    float ys[8] = {ya.x, ya.y, ya.z, ya.w, yb.x, yb.y, yb.z, yb.w};
    int lo[8] = {0,0,0,0,0,0,0,0};
    // branch-free lower_bound, 8 searches interleaved for latency overlap
    #pragma unroll
    for (int step = 1024; step > 0; step >>= 1) {
        #pragma unroll
        for (int j = 0; j < 8; j++) {
            int c = lo[j] + step;
            if (c <= NSEG && s_nb[c - 1] < s[j]) lo[j] = c;
        }
    }
    #pragma unroll
    for (int j = 0; j < 8; j++) {
        int pos = lo[j] < NSEG ? lo[j] : NSEG - 1;   // clip (searchsorted semantics)
        if (s_nb[pos] == s[j]) {
            int seg  = layer * NSEG + pos;
            int rank = atomicAdd(&g_counts[seg], 1);
            if (rank < CAP)
                g_ew[(seg << 10) + rank] = make_int2(ds[j], __float_as_int(ys[j] - BASELINE));
        }
    }
}

// ---------------- K2: mega kernel — accum + attention (+softmax on last attn block) -
__global__ void __launch_bounds__(256) k_mega(const float4* __restrict__ drugs,
                                              float4* __restrict__ msgs,
                                              const float* __restrict__ form_f,
                                              const float* __restrict__ role_f,
                                              const float* __restrict__ W1,
                                              const float* __restrict__ W2,
                                              const float* __restrict__ b2) {
    __shared__ float sf[4][PD];
    __shared__ float sred[4][2];
    if (blockIdx.x < ACCB) {
        // ---- gather + accumulate: 2 segments per block, 128 threads each ----
        int t = threadIdx.x & 127;
        int seg = blockIdx.x * 2 + (threadIdx.x >> 7);
        int cnt = min(g_counts[seg], CAP);
        const int2* ew = g_ew + (seg << 10);       // 16B-aligned base
        float4 a0 = {0.f,0.f,0.f,0.f}, a1 = a0, a2 = a0, a3 = a0;
        int e = 0;
        for (; e + 7 < cnt; e += 8) {
            int4 p0 = *(const int4*)(ew + e);
            int4 p1 = *(const int4*)(ew + e + 2);
            int4 p2 = *(const int4*)(ew + e + 4);
            int4 p3 = *(const int4*)(ew + e + 6);
            float4 r0 = drugs[(size_t)p0.x * 128 + t];
            float4 r1 = drugs[(size_t)p0.z * 128 + t];
            float4 r2 = drugs[(size_t)p1.x * 128 + t];
            float4 r3 = drugs[(size_t)p1.z * 128 + t];
            float4 r4 = drugs[(size_t)p2.x * 128 + t];
            float4 r5 = drugs[(size_t)p2.z * 128 + t];
            float4 r6 = drugs[(size_t)p3.x * 128 + t];
            float4 r7 = drugs[(size_t)p3.z * 128 + t];
            float w0 = __int_as_float(p0.y), w1 = __int_as_float(p0.w);
            float w2 = __int_as_float(p1.y), w3 = __int_as_float(p1.w);
            float w4 = __int_as_float(p2.y), w5 = __int_as_float(p2.w);
            float w6 = __int_as_float(p3.y), w7 = __int_as_float(p3.w);
            a0.x += w0*r0.x; a0.y += w0*r0.y; a0.z += w0*r0.z; a0.w += w0*r0.w;
            a1.x += w1*r1.x; a1.y += w1*r1.y; a1.z += w1*r1.z; a1.w += w1*r1.w;
            a2.x += w2*r2.x; a2.y += w2*r2.y; a2.z += w2*r2.z; a2.w += w2*r2.w;
            a3.x += w3*r3.x; a3.y += w3*r3.y; a3.z += w3*r3.z; a3.w += w3*r3.w;
            a0.x += w4*r4.x; a0.y += w4*r4.y; a0.z += w4*r4.z; a0.w += w4*r4.w;
            a1.x += w5*r5.x; a1.y += w5*r5.y; a1.z += w5*r5.z; a1.w += w5*r5.w;
            a2.x += w6*r6.x; a2.y += w6*r6.y; a2.z += w6*r6.z; a2.w += w6*r6.w;
            a3.x += w7*r7.x; a3.y += w7*r7.y; a3.z += w7*r7.z; a3.w += w7*r7.w;
        }
        for (; e < cnt; e++) {
            int2 p = ew[e];
            float w = __int_as_float(p.y);
            float4 r = drugs[(size_t)p.x * 128 + t];
            a0.x += w*r.x; a0.y += w*r.y; a0.z += w*r.z; a0.w += w*r.w;
        }
        a0.x += a1.x + a2.x + a3.x;
        a0.y += a1.y + a2.y + a3.y;
        a0.z += a1.z + a2.z + a3.z;
        a0.w += a1.w + a2.w + a3.w;
        msgs[(size_t)seg * 128 + t] = a0;
    } else {
        // ---- attention logits: 4 rows per block, 64 threads per row ----
        int g = threadIdx.x >> 6;
        int t = threadIdx.x & 63;
        int row = (blockIdx.x - ACCB) * 4 + g;
        int l = (row >= NSEG) ? 1 : 0;
        const float* feat = l ? role_f + (size_t)(row - NSEG) * PD
                              : form_f + (size_t)row * PD;
        float4* s4 = (float4*)sf[g];
        const float4* f4 = (const float4*)feat;
        s4[t]      = f4[t];
        s4[t + 64] = f4[t + 64];
        __syncthreads();
        float acc = g_tpart[l * 64 + t];
        const float* Wp = W1 + PD * 64 + t;        // rows 512..1023 of W1, column t
        const float4* sfv = (const float4*)sf[g];
        #pragma unroll 4
        for (int k4 = 0; k4 < PD / 4; k4++) {
            float4 s = sfv[k4];
            int k = k4 * 4;
            acc += s.x * Wp[k * 64] + s.y * Wp[(k + 1) * 64]
                 + s.z * Wp[(k + 2) * 64] + s.w * Wp[(k + 3) * 64];
        }
        acc = acc > 0.f ? acc : 0.2f * acc;        // LeakyReLU(0.2)
        float p = acc * W2[t];
        #pragma unroll
        for (int o = 16; o > 0; o >>= 1) p += __shfl_down_sync(0xffffffffu, p, o);
        if ((t & 31) == 0) sred[g][t >> 5] = p;
        __syncthreads();
        if (t == 0) g_logits[row] = sred[g][0] + sred[g][1] + b2[0];

        // ---- last attention block converts logits -> softmax weights in-place.
        //      Runs inside the shadow of the long accum blocks: effectively free.
        __shared__ unsigned s_last;
        __shared__ float s_r[8];
        __syncthreads();
        __threadfence();
        if (threadIdx.x == 0)
            s_last = (atomicAdd(&g_aticket, 1) == (ATTB - 1)) ? 1u : 0u;
        __syncthreads();
        if (!s_last) return;
        __threadfence();                       // order our logit reads after others' writes
        int tt = threadIdx.x;                  // 256 threads
        int lane = tt & 31, warp = tt >> 5;
        if (tt == 0) g_aticket = 0;            // reset for next graph replay
        float m = -1e30f;
        for (int i = tt; i < NSEG2; i += 256) m = fmaxf(m, g_logits[i]);
        #pragma unroll
        for (int o = 16; o > 0; o >>= 1) m = fmaxf(m, __shfl_xor_sync(0xffffffffu, m, o));
        if (lane == 0) s_r[warp] = m;
        __syncthreads();
        float mx = s_r[0];
        #pragma unroll
        for (int w = 1; w < 8; w++) mx = fmaxf(mx, s_r[w]);
        float ssum = 0.f;
        for (int i = tt; i < NSEG2; i += 256) ssum += expf(g_logits[i] - mx);
        #pragma unroll
        for (int o = 16; o > 0; o >>= 1) ssum += __shfl_xor_sync(0xffffffffu, ssum, o);
        __syncthreads();
        if (lane == 0) s_r[warp] = ssum;
        __syncthreads();
        float tot = 0.f;
        #pragma unroll
        for (int w = 0; w < 8; w++) tot += s_r[w];
        float inv = 1.f / tot;
        for (int i = tt; i < NSEG2; i += 256) g_logits[i] = expf(g_logits[i] - mx) * inv;
    }
}

// ---------------- K3: vprior partials (streaming) + re-zero counts for next call ----
__global__ void __launch_bounds__(128) k_vprior(const float4* __restrict__ msgs) {
    int t = threadIdx.x;
    int r0 = blockIdx.x * RPB;
    float4 a = {0.f, 0.f, 0.f, 0.f};
    #pragma unroll
    for (int j = 0; j < RPB; j++) {       // fully unrolled: all 40 loads in flight
        float w = g_logits[r0 + j];       // already softmax-normalized
        float4 v = __ldcs(&msgs[(size_t)(r0 + j) * 128 + t]);
        a.x += w * v.x; a.y += w * v.y; a.z += w * v.z; a.w += w * v.w;
    }
    *(float4*)&g_vpart[blockIdx.x][t * 4] = a;
    int idx = blockIdx.x * 128 + t;       // re-zero counts for the next invocation
    if (idx < NSEG2) g_counts[idx] = 0;   // (mega already consumed them this call)
}

// ---------------- K4: reduce partials + MLP + residual + LayerNorm -----------------
__global__ void __launch_bounds__(512) k_final(const float* __restrict__ target,
                                               const float* __restrict__ Wi1,
                                               const float* __restrict__ bi1,
                                               const float* __restrict__ alpha_p,
                                               const float* __restrict__ Wi2,
                                               const float* __restrict__ bi2,
                                               const float* __restrict__ gamma,
                                               const float* __restrict__ beta,
                                               float* __restrict__ out) {
    __shared__ float sv[PD];
    __shared__ float sh[PD];
    __shared__ float sred[512];
    int t = threadIdx.x;
    float s = 0.f;
    #pragma unroll 8
    for (int p = 0; p < NPART; p++) s += g_vpart[p][t];   // coalesced across threads
    sv[t] = s;
    __syncthreads();
    float h = bi1[t];
    #pragma unroll 8
    for (int k = 0; k < PD; k++) h += sv[k] * Wi1[k * PD + t];
    float alpha = alpha_p[0];
    h = h > 0.f ? h : alpha * h;          // PReLU
    sh[t] = h;
    __syncthreads();
    float v = bi2[t];
    #pragma unroll 8
    for (int k = 0; k < PD; k++) v += sh[k] * Wi2[k * PD + t];
    float x = target[t] + v;
    sred[t] = x; __syncthreads();
    for (int o = 256; o > 0; o >>= 1) { if (t < o) sred[t] += sred[t + o]; __syncthreads(); }
    float mu = sred[0] * (1.f / PD);
    __syncthreads();
    float d = x - mu;
    sred[t] = d * d; __syncthreads();
    for (int o = 256; o > 0; o >>= 1) { if (t < o) sred[t] += sred[t + o]; __syncthreads(); }
    float var = sred[0] * (1.f / PD);
    out[t] = (x - mu) * rsqrtf(var + LN_EPS) * gamma[t] + beta[t];
}

// ---------------- launch ----------------
extern "C" void kernel_launch(void* const* d_in, const int* in_sizes, int n_in,
                              void* d_out, int out_size) {
    const float* target = (const float*)d_in[0];
    const float* form_f = (const float*)d_in[1];
    const float* role_f = (const float*)d_in[2];
    const int*   nb_form = (const int*)d_in[3];
    const int*   nb_role = (const int*)d_in[4];
    const int*   ei_form = (const int*)d_in[5];
    const float* y_form  = (const float*)d_in[6];
    const int*   ei_role = (const int*)d_in[7];
    const float* y_role  = (const float*)d_in[8];
    const float* drugs   = (const float*)d_in[9];
    const float* lemb    = (const float*)d_in[10];
    const float* W1      = (const float*)d_in[11];
    const float* b1      = (const float*)d_in[12];
    const float* W2      = (const float*)d_in[13];
    const float* b2      = (const float*)d_in[14];
    const float* Wi1     = (const float*)d_in[15];
    const float* bi1     = (const float*)d_in[16];
    const float* alpha   = (const float*)d_in[17];
    const float* Wi2     = (const float*)d_in[18];
    const float* bi2     = (const float*)d_in[19];
    const float* gamma   = (const float*)d_in[20];
    const float* beta    = (const float*)d_in[21];

    float* out  = (float*)d_out;
    float* msgs = out + PD;   // [4000, 512]: form rows 0..1999, role rows 2000..3999

    dim3 gE8((EDG / 8 + 255) / 256, 3);   // y=0,1: edges (8/thread); y=2: tpart
    k_histscatter<<<gE8, 256>>>(nb_form, nb_role, ei_form, y_form, ei_role, y_role,
                                target, lemb, W1, b1);
    k_mega<<<ACCB + ATTB, 256>>>((const float4*)drugs, (float4*)msgs,
                                 form_f, role_f, W1, W2, b2);
    k_vprior<<<NPART, 128>>>((const float4*)msgs);
    k_final<<<1, 512>>>(target, Wi1, bi1, alpha, Wi2, bi2, gamma, beta, out);
}

// round 12
// speedup vs baseline: 1.2886x; 1.1394x over previous
#include <cuda_runtime.h>

#define PD     512        // protein_dim == drug_dim
#define NSEG   2000       // neighbors per layer
#define EDG    300000     // edges per layer
#define NSEG2  (2*NSEG)   // 4000 total segments
#define CAP    1024       // per-segment bucket capacity (avg fill ~150)
#define ACCB   (NSEG2/2)  // accum blocks in mega kernel (2 segments each)
#define ATTB   (NSEG2/4)  // attention blocks in mega kernel (4 rows each)
#define NPART  200        // vprior partial blocks
#define RPB    (NSEG2/NPART)  // 20 rows per vprior block
#define MLPB   32         // split-k blocks for the 512x512 matvecs
#define KROWS  (PD/MLPB)  // 16 k-rows per mlp block
#define BASELINE 6.0f
#define LN_EPS 1e-5f

// ---------------- device scratch (no allocations allowed) ----------------
__device__ int   g_counts[NSEG2];     // statically zero; re-zeroed by k_vprior each call
__device__ int2  g_ew[NSEG2 * CAP];   // {drug index, weight bits}, fixed-cap buckets
__device__ float g_logits[NSEG2];     // logits, overwritten in-place with softmax weights
__device__ float g_tpart[128];        // fixed part of attention hidden (target + layer_emb)
__device__ float g_vpart[NPART][PD];  // atomic-free vprior partials
__device__ float g_hpart1[MLPB][PD];  // split-k partials of h = sv @ Wi1
__device__ float g_hpart2[MLPB][PD];  // split-k partials of v = h @ Wi2
__device__ int   g_aticket = 0;       // attention-block completion ticket (self-resetting)

// ---------------- K1: fused hist+scatter (y=0,1) and tpart (y=2) -------------------
__global__ void __launch_bounds__(256) k_histscatter(const int* __restrict__ nb_form,
                                                     const int* __restrict__ nb_role,
                                                     const int* __restrict__ ei_form,
                                                     const float* __restrict__ y_form,
                                                     const int* __restrict__ ei_role,
                                                     const float* __restrict__ y_role,
                                                     const float* __restrict__ target,
                                                     const float* __restrict__ lemb,
                                                     const float* __restrict__ W1,
                                                     const float* __restrict__ b1) {
    const int layer = blockIdx.y;
    if (layer == 2) {
        // ---- attention fixed part: 1 block, 128 active threads ----
        if (blockIdx.x != 0) return;
        int t = threadIdx.x;
        if (t >= 128) return;
        int l = t >> 6, j = t & 63;
        float acc = b1[j];
        for (int k = 0; k < PD; k++) acc += target[k] * W1[k * 64 + j];
        for (int k = 0; k < 16; k++)  acc += lemb[l * 16 + k] * W1[(2 * PD + k) * 64 + j];
        g_tpart[t] = acc;
        return;
    }
    __shared__ int s_nb[NSEG];
    const int*   nb = layer ? nb_role : nb_form;
    const int*   ei = layer ? ei_role : ei_form;
    const float* yv = layer ? y_role  : y_form;
    for (int i = threadIdx.x; i < NSEG; i += 256) s_nb[i] = nb[i];
    __syncthreads();

    int e0 = (blockIdx.x * 256 + threadIdx.x) * 8;
    if (e0 >= EDG) return;                         // EDG % 8 == 0, full int4 pairs safe
    int4 va = *(const int4*)(ei + e0);             // ei[0][e0..]
    int4 vb = *(const int4*)(ei + e0 + 4);
    int4 da = *(const int4*)(ei + EDG + e0);       // ei[1][e0..]
    int4 db = *(const int4*)(ei + EDG + e0 + 4);
    float4 ya = *(const float4*)(yv + e0);
    float4 yb = *(const float4*)(yv + e0 + 4);
    int s[8]  = {va.x, va.y, va.z, va.w, vb.x, vb.y, vb.z, vb.w};
    int ds[8] = {da.x, da.y, da.z, da.w, db.x, db.y, db.z, db.w};
    float ys[8] = {ya.x, ya.y, ya.z, ya.w, yb.x, yb.y, yb.z, yb.w};
    int lo[8] = {0,0,0,0,0,0,0,0};
    // branch-free lower_bound, 8 searches interleaved for latency overlap
    #pragma unroll
    for (int step = 1024; step > 0; step >>= 1) {
        #pragma unroll
        for (int j = 0; j < 8; j++) {
            int c = lo[j] + step;
            if (c <= NSEG && s_nb[c - 1] < s[j]) lo[j] = c;
        }
    }
    #pragma unroll
    for (int j = 0; j < 8; j++) {
        int pos = lo[j] < NSEG ? lo[j] : NSEG - 1;   // clip (searchsorted semantics)
        if (s_nb[pos] == s[j]) {
            int seg  = layer * NSEG + pos;
            int rank = atomicAdd(&g_counts[seg], 1);
            if (rank < CAP)
                g_ew[(seg << 10) + rank] = make_int2(ds[j], __float_as_int(ys[j] - BASELINE));
        }
    }
}

// ---------------- K2: mega kernel — accum + attention (+softmax on last attn block) -
__global__ void __launch_bounds__(256) k_mega(const float4* __restrict__ drugs,
                                              float4* __restrict__ msgs,
                                              const float* __restrict__ form_f,
                                              const float* __restrict__ role_f,
                                              const float* __restrict__ W1,
                                              const float* __restrict__ W2,
                                              const float* __restrict__ b2) {
    __shared__ float sf[4][PD];
    __shared__ float sred[4][2];
    if (blockIdx.x < ACCB) {
        // ---- gather + accumulate: 2 segments per block, 128 threads each ----
        int t = threadIdx.x & 127;
        int seg = blockIdx.x * 2 + (threadIdx.x >> 7);
        int cnt = min(g_counts[seg], CAP);
        const int2* ew = g_ew + (seg << 10);       // 16B-aligned base
        float4 a0 = {0.f,0.f,0.f,0.f}, a1 = a0, a2 = a0, a3 = a0;
        int e = 0;
        for (; e + 7 < cnt; e += 8) {
            int4 p0 = *(const int4*)(ew + e);
            int4 p1 = *(const int4*)(ew + e + 2);
            int4 p2 = *(const int4*)(ew + e + 4);
            int4 p3 = *(const int4*)(ew + e + 6);
            float4 r0 = drugs[(size_t)p0.x * 128 + t];
            float4 r1 = drugs[(size_t)p0.z * 128 + t];
            float4 r2 = drugs[(size_t)p1.x * 128 + t];
            float4 r3 = drugs[(size_t)p1.z * 128 + t];
            float4 r4 = drugs[(size_t)p2.x * 128 + t];
            float4 r5 = drugs[(size_t)p2.z * 128 + t];
            float4 r6 = drugs[(size_t)p3.x * 128 + t];
            float4 r7 = drugs[(size_t)p3.z * 128 + t];
            float w0 = __int_as_float(p0.y), w1 = __int_as_float(p0.w);
            float w2 = __int_as_float(p1.y), w3 = __int_as_float(p1.w);
            float w4 = __int_as_float(p2.y), w5 = __int_as_float(p2.w);
            float w6 = __int_as_float(p3.y), w7 = __int_as_float(p3.w);
            a0.x += w0*r0.x; a0.y += w0*r0.y; a0.z += w0*r0.z; a0.w += w0*r0.w;
            a1.x += w1*r1.x; a1.y += w1*r1.y; a1.z += w1*r1.z; a1.w += w1*r1.w;
            a2.x += w2*r2.x; a2.y += w2*r2.y; a2.z += w2*r2.z; a2.w += w2*r2.w;
            a3.x += w3*r3.x; a3.y += w3*r3.y; a3.z += w3*r3.z; a3.w += w3*r3.w;
            a0.x += w4*r4.x; a0.y += w4*r4.y; a0.z += w4*r4.z; a0.w += w4*r4.w;
            a1.x += w5*r5.x; a1.y += w5*r5.y; a1.z += w5*r5.z; a1.w += w5*r5.w;
            a2.x += w6*r6.x; a2.y += w6*r6.y; a2.z += w6*r6.z; a2.w += w6*r6.w;
            a3.x += w7*r7.x; a3.y += w7*r7.y; a3.z += w7*r7.z; a3.w += w7*r7.w;
        }
        for (; e < cnt; e++) {
            int2 p = ew[e];
            float w = __int_as_float(p.y);
            float4 r = drugs[(size_t)p.x * 128 + t];
            a0.x += w*r.x; a0.y += w*r.y; a0.z += w*r.z; a0.w += w*r.w;
        }
        a0.x += a1.x + a2.x + a3.x;
        a0.y += a1.y + a2.y + a3.y;
        a0.z += a1.z + a2.z + a3.z;
        a0.w += a1.w + a2.w + a3.w;
        msgs[(size_t)seg * 128 + t] = a0;
    } else {
        // ---- attention logits: 4 rows per block, 64 threads per row ----
        int g = threadIdx.x >> 6;
        int t = threadIdx.x & 63;
        int row = (blockIdx.x - ACCB) * 4 + g;
        int l = (row >= NSEG) ? 1 : 0;
        const float* feat = l ? role_f + (size_t)(row - NSEG) * PD
                              : form_f + (size_t)row * PD;
        float4* s4 = (float4*)sf[g];
        const float4* f4 = (const float4*)feat;
        s4[t]      = f4[t];
        s4[t + 64] = f4[t + 64];
        __syncthreads();
        float acc = g_tpart[l * 64 + t];
        const float* Wp = W1 + PD * 64 + t;        // rows 512..1023 of W1, column t
        const float4* sfv = (const float4*)sf[g];
        #pragma unroll 4
        for (int k4 = 0; k4 < PD / 4; k4++) {
            float4 s = sfv[k4];
            int k = k4 * 4;
            acc += s.x * Wp[k * 64] + s.y * Wp[(k + 1) * 64]
                 + s.z * Wp[(k + 2) * 64] + s.w * Wp[(k + 3) * 64];
        }
        acc = acc > 0.f ? acc : 0.2f * acc;        // LeakyReLU(0.2)
        float p = acc * W2[t];
        #pragma unroll
        for (int o = 16; o > 0; o >>= 1) p += __shfl_down_sync(0xffffffffu, p, o);
        if ((t & 31) == 0) sred[g][t >> 5] = p;
        __syncthreads();
        if (t == 0) g_logits[row] = sred[g][0] + sred[g][1] + b2[0];

        // ---- last attention block converts logits -> softmax weights in-place.
        //      Runs inside the shadow of the long accum blocks: effectively free.
        __shared__ unsigned s_last;
        __shared__ float s_r[8];
        __syncthreads();
        __threadfence();
        if (threadIdx.x == 0)
            s_last = (atomicAdd(&g_aticket, 1) == (ATTB - 1)) ? 1u : 0u;
        __syncthreads();
        if (!s_last) return;
        __threadfence();                       // order our logit reads after others' writes
        int tt = threadIdx.x;                  // 256 threads
        int lane = tt & 31, warp = tt >> 5;
        if (tt == 0) g_aticket = 0;            // reset for next graph replay
        float m = -1e30f;
        for (int i = tt; i < NSEG2; i += 256) m = fmaxf(m, g_logits[i]);
        #pragma unroll
        for (int o = 16; o > 0; o >>= 1) m = fmaxf(m, __shfl_xor_sync(0xffffffffu, m, o));
        if (lane == 0) s_r[warp] = m;
        __syncthreads();
        float mx = s_r[0];
        #pragma unroll
        for (int w = 1; w < 8; w++) mx = fmaxf(mx, s_r[w]);
        float ssum = 0.f;
        for (int i = tt; i < NSEG2; i += 256) ssum += expf(g_logits[i] - mx);
        #pragma unroll
        for (int o = 16; o > 0; o >>= 1) ssum += __shfl_xor_sync(0xffffffffu, ssum, o);
        __syncthreads();
        if (lane == 0) s_r[warp] = ssum;
        __syncthreads();
        float tot = 0.f;
        #pragma unroll
        for (int w = 0; w < 8; w++) tot += s_r[w];
        float inv = 1.f / tot;
        for (int i = tt; i < NSEG2; i += 256) g_logits[i] = expf(g_logits[i] - mx) * inv;
    }
}

// ---------------- K3: vprior partials (streaming) + re-zero counts for next call ----
__global__ void __launch_bounds__(128) k_vprior(const float4* __restrict__ msgs) {
    int t = threadIdx.x;
    int r0 = blockIdx.x * RPB;
    float4 a = {0.f, 0.f, 0.f, 0.f};
    #pragma unroll
    for (int j = 0; j < RPB; j++) {       // fully unrolled: all 40 loads in flight
        float w = g_logits[r0 + j];       // already softmax-normalized
        float4 v = __ldcs(&msgs[(size_t)(r0 + j) * 128 + t]);
        a.x += w * v.x; a.y += w * v.y; a.z += w * v.z; a.w += w * v.w;
    }
    *(float4*)&g_vpart[blockIdx.x][t * 4] = a;
    int idx = blockIdx.x * 128 + t;       // re-zero counts for the next invocation
    if (idx < NSEG2) g_counts[idx] = 0;   // (mega already consumed them this call)
}

// ---------------- K4: split-k partial of h = v_prior @ Wi1 -------------------------
__global__ void __launch_bounds__(512) k_mlp1(const float* __restrict__ Wi1) {
    __shared__ float ssv[PD];
    int t = threadIdx.x;
    // every block redundantly reduces the vprior partials (reads hit L2)
    float s = 0.f;
    #pragma unroll 8
    for (int p = 0; p < NPART; p++) s += g_vpart[p][t];
    ssv[t] = s;
    __syncthreads();
    int k0 = blockIdx.x * KROWS;
    const float* W = Wi1 + (size_t)k0 * PD + t;   // block-distinct 16 rows, coalesced
    float h = 0.f;
    #pragma unroll
    for (int k = 0; k < KROWS; k++)
        h += ssv[k0 + k] * W[k * PD];
    g_hpart1[blockIdx.x][t] = h;
}

// ---------------- K5: reduce h partials, PReLU, split-k partial of v = h @ Wi2 -----
__global__ void __launch_bounds__(512) k_mlp2(const float* __restrict__ Wi2,
                                              const float* __restrict__ bi1,
                                              const float* __restrict__ alpha_p) {
    __shared__ float sh[PD];
    int t = threadIdx.x;
    float h = bi1[t];
    #pragma unroll
    for (int b = 0; b < MLPB; b++) h += g_hpart1[b][t];
    float alpha = alpha_p[0];
    sh[t] = h > 0.f ? h : alpha * h;              // PReLU
    __syncthreads();
    int k0 = blockIdx.x * KROWS;
    const float* W = Wi2 + (size_t)k0 * PD + t;
    float v = 0.f;
    #pragma unroll
    for (int k = 0; k < KROWS; k++)
        v += sh[k0 + k] * W[k * PD];
    g_hpart2[blockIdx.x][t] = v;
}

// ---------------- K6: reduce v partials + residual + LayerNorm ---------------------
__global__ void __launch_bounds__(512) k_fin(const float* __restrict__ target,
                                             const float* __restrict__ bi2,
                                             const float* __restrict__ gamma,
                                             const float* __restrict__ beta,
                                             float* __restrict__ out) {
    __shared__ float sred[512];
    int t = threadIdx.x;
    float v = bi2[t];
    #pragma unroll
    for (int b = 0; b < MLPB; b++) v += g_hpart2[b][t];
    float x = target[t] + v;
    sred[t] = x; __syncthreads();
    for (int o = 256; o > 0; o >>= 1) { if (t < o) sred[t] += sred[t + o]; __syncthreads(); }
    float mu = sred[0] * (1.f / PD);
    __syncthreads();
    float d = x - mu;
    sred[t] = d * d; __syncthreads();
    for (int o = 256; o > 0; o >>= 1) { if (t < o) sred[t] += sred[t + o]; __syncthreads(); }
    float var = sred[0] * (1.f / PD);
    out[t] = (x - mu) * rsqrtf(var + LN_EPS) * gamma[t] + beta[t];
}

// ---------------- launch ----------------
extern "C" void kernel_launch(void* const* d_in, const int* in_sizes, int n_in,
                              void* d_out, int out_size) {
    const float* target = (const float*)d_in[0];
    const float* form_f = (const float*)d_in[1];
    const float* role_f = (const float*)d_in[2];
    const int*   nb_form = (const int*)d_in[3];
    const int*   nb_role = (const int*)d_in[4];
    const int*   ei_form = (const int*)d_in[5];
    const float* y_form  = (const float*)d_in[6];
    const int*   ei_role = (const int*)d_in[7];
    const float* y_role  = (const float*)d_in[8];
    const float* drugs   = (const float*)d_in[9];
    const float* lemb    = (const float*)d_in[10];
    const float* W1      = (const float*)d_in[11];
    const float* b1      = (const float*)d_in[12];
    const float* W2      = (const float*)d_in[13];
    const float* b2      = (const float*)d_in[14];
    const float* Wi1     = (const float*)d_in[15];
    const float* bi1     = (const float*)d_in[16];
    const float* alpha   = (const float*)d_in[17];
    const float* Wi2     = (const float*)d_in[18];
    const float* bi2     = (const float*)d_in[19];
    const float* gamma   = (const float*)d_in[20];
    const float* beta    = (const float*)d_in[21];

    float* out  = (float*)d_out;
    float* msgs = out + PD;   // [4000, 512]: form rows 0..1999, role rows 2000..3999

    dim3 gE8((EDG / 8 + 255) / 256, 3);   // y=0,1: edges (8/thread); y=2: tpart
    k_histscatter<<<gE8, 256>>>(nb_form, nb_role, ei_form, y_form, ei_role, y_role,
                                target, lemb, W1, b1);
    k_mega<<<ACCB + ATTB, 256>>>((const float4*)drugs, (float4*)msgs,
                                 form_f, role_f, W1, W2, b2);
    k_vprior<<<NPART, 128>>>((const float4*)msgs);
    k_mlp1<<<MLPB, 512>>>(Wi1);
    k_mlp2<<<MLPB, 512>>>(Wi2, bi1, alpha);
    k_fin<<<1, 512>>>(target, bi2, gamma, beta, out);
}

// round 13
// speedup vs baseline: 1.3333x; 1.0347x over previous
#include <cuda_runtime.h>

#define PD     512        // protein_dim == drug_dim
#define NSEG   2000       // neighbors per layer
#define EDG    300000     // edges per layer
#define NSEG2  (2*NSEG)   // 4000 total segments
#define CAP    1024       // per-segment bucket capacity (avg fill ~150)
#define ACCB   (NSEG2/2)  // accum blocks in mega kernel (2 segments each)
#define ATTB   (NSEG2/4)  // attention blocks in mega kernel (4 rows each)
#define NPART  200        // vprior partial blocks
#define RPB    (NSEG2/NPART)  // 20 rows per vprior block
#define MLPB   32         // split-k blocks for the 512x512 matvecs
#define KROWS  (PD/MLPB)  // 16 k-rows per mlp block
#define BASELINE 6.0f
#define LN_EPS 1e-5f

// ---------------- device scratch (no allocations allowed) ----------------
__device__ int   g_counts[NSEG2];     // statically zero; re-zeroed by k_vprior each call
__device__ int2  g_ew[NSEG2 * CAP];   // {drug index, weight bits}, fixed-cap buckets
__device__ float g_logits[NSEG2];     // logits, overwritten in-place with softmax weights
__device__ float g_tpart[128];        // fixed part of attention hidden (target + layer_emb)
__device__ float g_vpart[NPART][PD];  // atomic-free vprior partials
__device__ float g_hpart1[MLPB][PD];  // split-k partials of h = sv @ Wi1
__device__ float g_hpart2[MLPB][PD];  // split-k partials of v = h @ Wi2
__device__ int   g_aticket = 0;       // attention-block completion ticket (self-resetting)

// ---------------- K1: fused hist+scatter (y=0,1) and tpart (y=2) -------------------
__global__ void __launch_bounds__(256) k_histscatter(const int* __restrict__ nb_form,
                                                     const int* __restrict__ nb_role,
                                                     const int* __restrict__ ei_form,
                                                     const float* __restrict__ y_form,
                                                     const int* __restrict__ ei_role,
                                                     const float* __restrict__ y_role,
                                                     const float* __restrict__ target,
                                                     const float* __restrict__ lemb,
                                                     const float* __restrict__ W1,
                                                     const float* __restrict__ b1) {
    const int layer = blockIdx.y;
    if (layer == 2) {
        // ---- attention fixed part: 1 block, 128 active threads ----
        if (blockIdx.x != 0) return;
        int t = threadIdx.x;
        if (t >= 128) return;
        int l = t >> 6, j = t & 63;
        float acc = b1[j];
        for (int k = 0; k < PD; k++) acc += target[k] * W1[k * 64 + j];
        for (int k = 0; k < 16; k++)  acc += lemb[l * 16 + k] * W1[(2 * PD + k) * 64 + j];
        g_tpart[t] = acc;
        return;
    }
    __shared__ int s_nb[NSEG];
    const int*   nb = layer ? nb_role : nb_form;
    const int*   ei = layer ? ei_role : ei_form;
    const float* yv = layer ? y_role  : y_form;
    for (int i = threadIdx.x; i < NSEG; i += 256) s_nb[i] = nb[i];
    __syncthreads();

    int e0 = (blockIdx.x * 256 + threadIdx.x) * 8;
    if (e0 >= EDG) return;                         // EDG % 8 == 0, full int4 pairs safe
    int4 va = *(const int4*)(ei + e0);             // ei[0][e0..]
    int4 vb = *(const int4*)(ei + e0 + 4);
    int4 da = *(const int4*)(ei + EDG + e0);       // ei[1][e0..]
    int4 db = *(const int4*)(ei + EDG + e0 + 4);
    float4 ya = *(const float4*)(yv + e0);
    float4 yb = *(const float4*)(yv + e0 + 4);
    int s[8]  = {va.x, va.y, va.z, va.w, vb.x, vb.y, vb.z, vb.w};
    int ds[8] = {da.x, da.y, da.z, da.w, db.x, db.y, db.z, db.w};
    float ys[8] = {ya.x, ya.y, ya.z, ya.w, yb.x, yb.y, yb.z, yb.w};
    int lo[8] = {0,0,0,0,0,0,0,0};
    // branch-free lower_bound, 8 searches interleaved for latency overlap
    #pragma unroll
    for (int step = 1024; step > 0; step >>= 1) {
        #pragma unroll
        for (int j = 0; j < 8; j++) {
            int c = lo[j] + step;
            if (c <= NSEG && s_nb[c - 1] < s[j]) lo[j] = c;
        }
    }
    #pragma unroll
    for (int j = 0; j < 8; j++) {
        int pos = lo[j] < NSEG ? lo[j] : NSEG - 1;   // clip (searchsorted semantics)
        if (s_nb[pos] == s[j]) {
            int seg  = layer * NSEG + pos;
            int rank = atomicAdd(&g_counts[seg], 1);
            if (rank < CAP)
                g_ew[(seg << 10) + rank] = make_int2(ds[j], __float_as_int(ys[j] - BASELINE));
        }
    }
}

// ---------------- K2: mega kernel — accum + attention (+softmax on last attn block) -
__global__ void __launch_bounds__(256) k_mega(const float4* __restrict__ drugs,
                                              float4* __restrict__ msgs,
                                              const float* __restrict__ form_f,
                                              const float* __restrict__ role_f,
                                              const float* __restrict__ W1,
                                              const float* __restrict__ W2,
                                              const float* __restrict__ b2) {
    __shared__ float sf[4][PD];
    __shared__ float sred[4][2];
    if (blockIdx.x < ACCB) {
        // ---- gather + accumulate: 2 segments per block, 128 threads each ----
        int t = threadIdx.x & 127;
        int seg = blockIdx.x * 2 + (threadIdx.x >> 7);
        int cnt = min(g_counts[seg], CAP);
        const int2* ew = g_ew + (seg << 10);       // 16B-aligned base
        float4 a0 = {0.f,0.f,0.f,0.f}, a1 = a0, a2 = a0, a3 = a0;
        int e = 0;
        for (; e + 7 < cnt; e += 8) {
            int4 p0 = *(const int4*)(ew + e);
            int4 p1 = *(const int4*)(ew + e + 2);
            int4 p2 = *(const int4*)(ew + e + 4);
            int4 p3 = *(const int4*)(ew + e + 6);
            float4 r0 = drugs[(size_t)p0.x * 128 + t];
            float4 r1 = drugs[(size_t)p0.z * 128 + t];
            float4 r2 = drugs[(size_t)p1.x * 128 + t];
            float4 r3 = drugs[(size_t)p1.z * 128 + t];
            float4 r4 = drugs[(size_t)p2.x * 128 + t];
            float4 r5 = drugs[(size_t)p2.z * 128 + t];
            float4 r6 = drugs[(size_t)p3.x * 128 + t];
            float4 r7 = drugs[(size_t)p3.z * 128 + t];
            float w0 = __int_as_float(p0.y), w1 = __int_as_float(p0.w);
            float w2 = __int_as_float(p1.y), w3 = __int_as_float(p1.w);
            float w4 = __int_as_float(p2.y), w5 = __int_as_float(p2.w);
            float w6 = __int_as_float(p3.y), w7 = __int_as_float(p3.w);
            a0.x += w0*r0.x; a0.y += w0*r0.y; a0.z += w0*r0.z; a0.w += w0*r0.w;
            a1.x += w1*r1.x; a1.y += w1*r1.y; a1.z += w1*r1.z; a1.w += w1*r1.w;
            a2.x += w2*r2.x; a2.y += w2*r2.y; a2.z += w2*r2.z; a2.w += w2*r2.w;
            a3.x += w3*r3.x; a3.y += w3*r3.y; a3.z += w3*r3.z; a3.w += w3*r3.w;
            a0.x += w4*r4.x; a0.y += w4*r4.y; a0.z += w4*r4.z; a0.w += w4*r4.w;
            a1.x += w5*r5.x; a1.y += w5*r5.y; a1.z += w5*r5.z; a1.w += w5*r5.w;
            a2.x += w6*r6.x; a2.y += w6*r6.y; a2.z += w6*r6.z; a2.w += w6*r6.w;
            a3.x += w7*r7.x; a3.y += w7*r7.y; a3.z += w7*r7.z; a3.w += w7*r7.w;
        }
        for (; e < cnt; e++) {
            int2 p = ew[e];
            float w = __int_as_float(p.y);
            float4 r = drugs[(size_t)p.x * 128 + t];
            a0.x += w*r.x; a0.y += w*r.y; a0.z += w*r.z; a0.w += w*r.w;
        }
        a0.x += a1.x + a2.x + a3.x;
        a0.y += a1.y + a2.y + a3.y;
        a0.z += a1.z + a2.z + a3.z;
        a0.w += a1.w + a2.w + a3.w;
        msgs[(size_t)seg * 128 + t] = a0;
    } else {
        // ---- attention logits: 4 rows per block, 64 threads per row ----
        int g = threadIdx.x >> 6;
        int t = threadIdx.x & 63;
        int row = (blockIdx.x - ACCB) * 4 + g;
        int l = (row >= NSEG) ? 1 : 0;
        const float* feat = l ? role_f + (size_t)(row - NSEG) * PD
                              : form_f + (size_t)row * PD;
        float4* s4 = (float4*)sf[g];
        const float4* f4 = (const float4*)feat;
        s4[t]      = f4[t];
        s4[t + 64] = f4[t + 64];
        __syncthreads();
        float acc = g_tpart[l * 64 + t];
        const float* Wp = W1 + PD * 64 + t;        // rows 512..1023 of W1, column t
        const float4* sfv = (const float4*)sf[g];
        #pragma unroll 4
        for (int k4 = 0; k4 < PD / 4; k4++) {
            float4 s = sfv[k4];
            int k = k4 * 4;
            acc += s.x * Wp[k * 64] + s.y * Wp[(k + 1) * 64]
                 + s.z * Wp[(k + 2) * 64] + s.w * Wp[(k + 3) * 64];
        }
        acc = acc > 0.f ? acc : 0.2f * acc;        // LeakyReLU(0.2)
        float p = acc * W2[t];
        #pragma unroll
        for (int o = 16; o > 0; o >>= 1) p += __shfl_down_sync(0xffffffffu, p, o);
        if ((t & 31) == 0) sred[g][t >> 5] = p;
        __syncthreads();
        if (t == 0) g_logits[row] = sred[g][0] + sred[g][1] + b2[0];

        // ---- last attention block converts logits -> softmax weights in-place.
        //      Runs inside the shadow of the long accum blocks: effectively free.
        __shared__ unsigned s_last;
        __shared__ float s_r[8];
        __syncthreads();
        __threadfence();
        if (threadIdx.x == 0)
            s_last = (atomicAdd(&g_aticket, 1) == (ATTB - 1)) ? 1u : 0u;
        __syncthreads();
        if (!s_last) return;
        __threadfence();                       // order our logit reads after others' writes
        int tt = threadIdx.x;                  // 256 threads
        int lane = tt & 31, warp = tt >> 5;
        if (tt == 0) g_aticket = 0;            // reset for next graph replay
        float m = -1e30f;
        for (int i = tt; i < NSEG2; i += 256) m = fmaxf(m, g_logits[i]);
        #pragma unroll
        for (int o = 16; o > 0; o >>= 1) m = fmaxf(m, __shfl_xor_sync(0xffffffffu, m, o));
        if (lane == 0) s_r[warp] = m;
        __syncthreads();
        float mx = s_r[0];
        #pragma unroll
        for (int w = 1; w < 8; w++) mx = fmaxf(mx, s_r[w]);
        float ssum = 0.f;
        for (int i = tt; i < NSEG2; i += 256) ssum += expf(g_logits[i] - mx);
        #pragma unroll
        for (int o = 16; o > 0; o >>= 1) ssum += __shfl_xor_sync(0xffffffffu, ssum, o);
        __syncthreads();
        if (lane == 0) s_r[warp] = ssum;
        __syncthreads();
        float tot = 0.f;
        #pragma unroll
        for (int w = 0; w < 8; w++) tot += s_r[w];
        float inv = 1.f / tot;
        for (int i = tt; i < NSEG2; i += 256) g_logits[i] = expf(g_logits[i] - mx) * inv;
    }
}

// ---------------- K3: vprior partials (streaming) + re-zero counts for next call ----
__global__ void __launch_bounds__(128) k_vprior(const float4* __restrict__ msgs) {
    int t = threadIdx.x;
    int r0 = blockIdx.x * RPB;
    float4 a = {0.f, 0.f, 0.f, 0.f};
    #pragma unroll
    for (int j = 0; j < RPB; j++) {       // fully unrolled: all 40 loads in flight
        float w = g_logits[r0 + j];       // already softmax-normalized
        float4 v = __ldcs(&msgs[(size_t)(r0 + j) * 128 + t]);
        a.x += w * v.x; a.y += w * v.y; a.z += w * v.z; a.w += w * v.w;
    }
    *(float4*)&g_vpart[blockIdx.x][t * 4] = a;
    int idx = blockIdx.x * 128 + t;       // re-zero counts for the next invocation
    if (idx < NSEG2) g_counts[idx] = 0;   // (mega already consumed them this call)
}

// ---------------- K4: split-k partial of h = v_prior @ Wi1 -------------------------
// Phase A: warp w reduces ONLY sv[k0+w] over the 200 vpart partials (need-only).
// Phase B: 16 coalesced Wi1 row loads per thread.
__global__ void __launch_bounds__(512) k_mlp1(const float* __restrict__ Wi1) {
    __shared__ float ssv[KROWS];
    int t = threadIdx.x;
    int w = t >> 5, lane = t & 31;        // 16 warps = KROWS rows
    int k0 = blockIdx.x * KROWS;
    float s = 0.f;
    for (int p = lane; p < NPART; p += 32) s += g_vpart[p][k0 + w];
    #pragma unroll
    for (int o = 16; o > 0; o >>= 1) s += __shfl_xor_sync(0xffffffffu, s, o);
    if (lane == 0) ssv[w] = s;
    __syncthreads();
    const float* W = Wi1 + (size_t)k0 * PD + t;   // block-distinct 16 rows, coalesced
    float h = 0.f;
    #pragma unroll
    for (int k = 0; k < KROWS; k++)
        h += ssv[k] * W[k * PD];
    g_hpart1[blockIdx.x][t] = h;
}

// ---------------- K5: reduce h partials (need-only), PReLU, partial of v = h @ Wi2 --
__global__ void __launch_bounds__(512) k_mlp2(const float* __restrict__ Wi2,
                                              const float* __restrict__ bi1,
                                              const float* __restrict__ alpha_p) {
    __shared__ float sh[KROWS];
    int t = threadIdx.x;
    int w = t >> 5, lane = t & 31;        // 16 warps = KROWS rows
    int k0 = blockIdx.x * KROWS;
    float h = g_hpart1[lane][k0 + w];     // 32 lanes cover all MLPB=32 partials
    #pragma unroll
    for (int o = 16; o > 0; o >>= 1) h += __shfl_xor_sync(0xffffffffu, h, o);
    if (lane == 0) {
        h += bi1[k0 + w];
        float alpha = alpha_p[0];
        sh[w] = h > 0.f ? h : alpha * h;  // PReLU
    }
    __syncthreads();
    const float* W = Wi2 + (size_t)k0 * PD + t;
    float v = 0.f;
    #pragma unroll
    for (int k = 0; k < KROWS; k++)
        v += sh[k] * W[k * PD];
    g_hpart2[blockIdx.x][t] = v;
}

// ---------------- K6: reduce v partials + residual + LayerNorm ---------------------
__global__ void __launch_bounds__(512) k_fin(const float* __restrict__ target,
                                             const float* __restrict__ bi2,
                                             const float* __restrict__ gamma,
                                             const float* __restrict__ beta,
                                             float* __restrict__ out) {
    __shared__ float sred[512];
    int t = threadIdx.x;
    float v = bi2[t];
    #pragma unroll
    for (int b = 0; b < MLPB; b++) v += g_hpart2[b][t];
    float x = target[t] + v;
    sred[t] = x; __syncthreads();
    for (int o = 256; o > 0; o >>= 1) { if (t < o) sred[t] += sred[t + o]; __syncthreads(); }
    float mu = sred[0] * (1.f / PD);
    __syncthreads();
    float d = x - mu;
    sred[t] = d * d; __syncthreads();
    for (int o = 256; o > 0; o >>= 1) { if (t < o) sred[t] += sred[t + o]; __syncthreads(); }
    float var = sred[0] * (1.f / PD);
    out[t] = (x - mu) * rsqrtf(var + LN_EPS) * gamma[t] + beta[t];
}

// ---------------- launch ----------------
extern "C" void kernel_launch(void* const* d_in, const int* in_sizes, int n_in,
                              void* d_out, int out_size) {
    const float* target = (const float*)d_in[0];
    const float* form_f = (const float*)d_in[1];
    const float* role_f = (const float*)d_in[2];
    const int*   nb_form = (const int*)d_in[3];
    const int*   nb_role = (const int*)d_in[4];
    const int*   ei_form = (const int*)d_in[5];
    const float* y_form  = (const float*)d_in[6];
    const int*   ei_role = (const int*)d_in[7];
    const float* y_role  = (const float*)d_in[8];
    const float* drugs   = (const float*)d_in[9];
    const float* lemb    = (const float*)d_in[10];
    const float* W1      = (const float*)d_in[11];
    const float* b1      = (const float*)d_in[12];
    const float* W2      = (const float*)d_in[13];
    const float* b2      = (const float*)d_in[14];
    const float* Wi1     = (const float*)d_in[15];
    const float* bi1     = (const float*)d_in[16];
    const float* alpha   = (const float*)d_in[17];
    const float* Wi2     = (const float*)d_in[18];
    const float* bi2     = (const float*)d_in[19];
    const float* gamma   = (const float*)d_in[20];
    const float* beta    = (const float*)d_in[21];

    float* out  = (float*)d_out;
    float* msgs = out + PD;   // [4000, 512]: form rows 0..1999, role rows 2000..3999

    dim3 gE8((EDG / 8 + 255) / 256, 3);   // y=0,1: edges (8/thread); y=2: tpart
    k_histscatter<<<gE8, 256>>>(nb_form, nb_role, ei_form, y_form, ei_role, y_role,
                                target, lemb, W1, b1);
    k_mega<<<ACCB + ATTB, 256>>>((const float4*)drugs, (float4*)msgs,
                                 form_f, role_f, W1, W2, b2);
    k_vprior<<<NPART, 128>>>((const float4*)msgs);
    k_mlp1<<<MLPB, 512>>>(Wi1);
    k_mlp2<<<MLPB, 512>>>(Wi2, bi1, alpha);
    k_fin<<<1, 512>>>(target, bi2, gamma, beta, out);
}